// round 13
// baseline (speedup 1.0000x reference)
#include <cuda_runtime.h>
#include <cuda_fp16.h>
#include <math.h>
#include <stdint.h>

#define BATCH 8
#define CDIM 512
#define HW 4096
#define CPG 16
#define EPSV 1e-6f

typedef __half h16;

// ---------------- device scratch ----------------
// g_nrm: [0..8) GN1 out, [8..16) GN2 out, each [b][t][c]
__device__ h16   g_nrm[(size_t)16 * HW * CDIM];
// g_qkp: [0..8) q proj, [8..16) k proj, each [b][t][c]
__device__ h16   g_qkp[(size_t)16 * HW * CDIM];
__device__ h16   g_w  [(size_t)4 * CDIM * CDIM];    // wq,wk,wv,wo fp16
__device__ float g_bqk[2 * CDIM];                   // bq | bk
__device__ h16   g_vp [(size_t)BATCH * CDIM * HW];  // v proj [b][c][t]
__device__ h16   g_ps [(size_t)16 * HW * CDIM];     // PV split partials [bz][t][c]
__device__ h16   g_ot [(size_t)BATCH * HW * CDIM];  // attn out [b][t][c]
__device__ h16   g_p  [(size_t)BATCH * HW * HW];    // E = exp(scale*S) [b][y][x]
__device__ float g_r  [(size_t)BATCH * HW];         // row sums of E

// ---------------- PTX helpers ----------------
__device__ __forceinline__ uint32_t smem_u32(const void* p) {
    uint32_t a;
    asm("{ .reg .u64 t; cvta.to.shared.u64 t, %1; cvt.u32.u64 %0, t; }" : "=r"(a) : "l"(p));
    return a;
}
__device__ __forceinline__ void cpa16(uint32_t d, const void* g) {
    asm volatile("cp.async.cg.shared.global [%0], [%1], 16;" :: "r"(d), "l"(g) : "memory");
}
__device__ __forceinline__ void ldm4(uint32_t* d, uint32_t addr) {
    asm volatile("ldmatrix.sync.aligned.m8n8.x4.shared.b16 {%0,%1,%2,%3}, [%4];"
                 : "=r"(d[0]), "=r"(d[1]), "=r"(d[2]), "=r"(d[3]) : "r"(addr));
}
#define MMA(d, a, b0, b1) \
    asm volatile("mma.sync.aligned.m16n8k16.row.col.f32.f16.f16.f32 " \
        "{%0,%1,%2,%3}, {%4,%5,%6,%7}, {%8,%9}, {%0,%1,%2,%3};" \
        : "+f"((d)[0]), "+f"((d)[1]), "+f"((d)[2]), "+f"((d)[3]) \
        : "r"((a)[0]), "r"((a)[1]), "r"((a)[2]), "r"((a)[3]), "r"(b0), "r"(b1))

// ---------------- fused double GroupNorm ----------------
__global__ __launch_bounds__(512)
void gn_fused(const float* __restrict__ x, h16* __restrict__ nrm,
              const float* __restrict__ gamma, const float* __restrict__ beta) {
    const int grp = blockIdx.x, b = blockIdx.y;
    const int c0 = grp * CPG;
    const size_t base = ((size_t)b * CDIM + c0) * HW;
    const int tid = threadIdx.x, wid = tid >> 5, lane = tid & 31;

    const float4* xc = (const float4*)(x + base + (size_t)wid * HW);
    float s = 0.f, ss = 0.f;
    for (int i = lane; i < HW / 4; i += 32) {
        float4 v = xc[i];
        s  += v.x + v.y + v.z + v.w;
        ss += v.x * v.x + v.y * v.y + v.z * v.z + v.w * v.w;
    }
#pragma unroll
    for (int o = 16; o; o >>= 1) {
        s  += __shfl_xor_sync(~0u, s, o);
        ss += __shfl_xor_sync(~0u, ss, o);
    }
    __shared__ float Sc[CPG], Qc[CPG];
    __shared__ float A1[CPG], B1[CPG], A2[CPG], B2[CPG];
    if (lane == 0) { Sc[wid] = s; Qc[wid] = ss; }
    __syncthreads();
    if (tid == 0) {
        float St = 0.f, Qt = 0.f;
        for (int c = 0; c < CPG; c++) { St += Sc[c]; Qt += Qc[c]; }
        const float invN = 1.f / (float)(CPG * HW);
        float mu1 = St * invN;
        float r1 = rsqrtf(Qt * invN - mu1 * mu1 + EPSV);
        float s2 = 0.f, q2 = 0.f;
        for (int c = 0; c < CPG; c++) {
            float a1 = gamma[c0 + c] * r1;
            float b1 = beta[c0 + c] - mu1 * a1;
            A1[c] = a1; B1[c] = b1;
            s2 += a1 * Sc[c] + (float)HW * b1;
            q2 += a1 * a1 * Qc[c] + 2.f * a1 * b1 * Sc[c] + (float)HW * b1 * b1;
        }
        float mu2 = s2 * invN;
        float r2 = rsqrtf(q2 * invN - mu2 * mu2 + EPSV);
        for (int c = 0; c < CPG; c++) {
            float g = gamma[c0 + c];
            A2[c] = g * r2 * A1[c];
            B2[c] = g * r2 * (B1[c] - mu2) + beta[c0 + c];
        }
    }
    __syncthreads();

    h16* qh = nrm + (size_t)b * HW * CDIM;
    h16* vh = nrm + (size_t)(8 + b) * HW * CDIM;
    for (int t = tid; t < HW; t += 512) {
        alignas(16) h16 h1[CPG], h2[CPG];
#pragma unroll
        for (int c = 0; c < CPG; c++) {
            float v = x[base + (size_t)c * HW + t];
            h1[c] = __float2half_rn(fmaf(v, A1[c], B1[c]));
            h2[c] = __float2half_rn(fmaf(v, A2[c], B2[c]));
        }
        size_t o = (size_t)t * CDIM + c0;
        *(uint4*)&qh[o] = *(uint4*)&h1[0]; *(uint4*)&qh[o + 8] = *(uint4*)&h1[8];
        *(uint4*)&vh[o] = *(uint4*)&h2[0]; *(uint4*)&vh[o + 8] = *(uint4*)&h2[8];
    }
}

// ---------------- weight fp32 -> fp16, bias pack, zero row sums ----------------
__global__ void wconv(const float* __restrict__ wq, const float* __restrict__ wk,
                      const float* __restrict__ wv, const float* __restrict__ wo,
                      const float* __restrict__ bq, const float* __restrict__ bk,
                      h16* __restrict__ out, float* __restrict__ bqk,
                      float* __restrict__ rz) {
    int e = blockIdx.x * 256 + threadIdx.x;
    int w = e >> 18, i = e & 0x3FFFF;
    const float* src = (w == 0) ? wq : (w == 1) ? wk : (w == 2) ? wv : wo;
    out[(size_t)w * 262144 + i] = __float2half_rn(src[i]);
    if (e < BATCH * HW) rz[e] = 0.f;
    if (e < 2 * CDIM) bqk[e] = (e < CDIM) ? bq[e] : bk[e - CDIM];
}

// ---------------- fp16 HMMA GEMM ----------------
// C[m][n] = f(alpha * sum_k A[m][k]*B[n][k])
// 128x128 block, BK=64, 3-stage cp.async, 8 warps (32x64 warp tiles)
// MODE 0: bz = batch
// MODE 1: merged pair: batch=bz&7, sel=bz>>3; A+=sel*mA, B+=sel*mB, C+=sel*mC, bias+=sel*CDIM
// MODE 2: split-K2: batch=bz>>1, sel=bz&1; A,B k-offset sel*K; C indexed by bz
#define SA_BYTES 16384
#define ST_BYTES 32768
#define SMEM_TOT (3 * ST_BYTES)

template <bool OUTF16, int BIAS, bool RES, bool EXPOUT, bool NRM, int MODE>
__global__ __launch_bounds__(256, 2)
void gemm16(const h16* __restrict__ A, size_t zA, int lda,
            const h16* __restrict__ B, size_t zB, int ldb,
            void* __restrict__ C, size_t zC, int ldC, int K,
            const float* __restrict__ bias,
            const float* __restrict__ res, size_t zR,
            float* __restrict__ rsum,
            float alpha, float oscale,
            size_t mA, size_t mB, size_t mC) {
    extern __shared__ __align__(16) char smem[];
    const int tid = threadIdx.x, lane = tid & 31, wid = tid >> 5;
    const int warp_m = wid & 3, warp_n = wid >> 2;
    const int bz = blockIdx.z;

    int batch = bz, sel = 0;
    if (MODE == 1) { batch = bz & 7; sel = bz >> 3; }
    if (MODE == 2) { batch = bz >> 1; sel = bz & 1; }

    const int m0 = blockIdx.y * 128, n0 = blockIdx.x * 128;
    const uint32_t sbase = smem_u32(smem);

    const h16* Ab = A + zA * batch
        + ((MODE == 1) ? (size_t)sel * mA : 0)
        + ((MODE == 2) ? (size_t)sel * K : 0);
    const h16* Bb = B + zB * batch
        + ((MODE == 1) ? (size_t)sel * mB : 0)
        + ((MODE == 2) ? (size_t)sel * K : 0);
    size_t coff;
    if (MODE == 1)      coff = zC * (size_t)batch + (size_t)sel * mC;
    else if (MODE == 2) coff = zC * (size_t)bz;
    else                coff = zC * (size_t)batch;
    if (MODE == 1 && BIAS == 2) bias += sel * CDIM;

    const int nst = K >> 6;

    auto load_stage = [&](int stage, int k0) {
        const uint32_t sA = sbase + stage * ST_BYTES;
        const uint32_t sB = sA + SA_BYTES;
#pragma unroll
        for (int i = 0; i < 4; i++) {
            const int c = tid + i * 256;
            const int row = c >> 3, u0 = c & 7;
            const uint32_t u = (uint32_t)u0 ^ (row & 7);
            cpa16(sA + row * 128 + u * 16, Ab + (size_t)(m0 + row) * lda + k0 + u0 * 8);
            cpa16(sB + row * 128 + u * 16, Bb + (size_t)(n0 + row) * ldb + k0 + u0 * 8);
        }
    };

    float acc[2][8][4];
#pragma unroll
    for (int i = 0; i < 2; i++)
#pragma unroll
        for (int j = 0; j < 8; j++)
#pragma unroll
            for (int l = 0; l < 4; l++) acc[i][j][l] = 0.f;

    load_stage(0, 0);
    asm volatile("cp.async.commit_group;" ::: "memory");
    load_stage(1, 64);
    asm volatile("cp.async.commit_group;" ::: "memory");

    const int g = lane >> 3, r = lane & 7;

    for (int s = 0; s < nst; s++) {
        asm volatile("cp.async.wait_group %0;" :: "n"(1) : "memory");
        __syncthreads();
        if (s + 2 < nst) load_stage((s + 2) % 3, (s + 2) << 6);
        asm volatile("cp.async.commit_group;" ::: "memory");

        const uint32_t sA = sbase + (s % 3) * ST_BYTES;
        const uint32_t sB = sA + SA_BYTES;
#pragma unroll
        for (int kk = 0; kk < 4; kk++) {
            const int c0 = kk * 16 + (g >> 1) * 8;
            const int uu = c0 >> 3;
            uint32_t af[2][4], bf[4][4];
#pragma unroll
            for (int mt = 0; mt < 2; mt++) {
                const int row = warp_m * 32 + mt * 16 + r + (g & 1) * 8;
                const uint32_t u = (uint32_t)uu ^ (row & 7);
                ldm4(af[mt], sA + row * 128 + u * 16);
            }
#pragma unroll
            for (int nt = 0; nt < 4; nt++) {
                const int row = warp_n * 64 + nt * 16 + r + (g & 1) * 8;
                const uint32_t u = (uint32_t)uu ^ (row & 7);
                ldm4(bf[nt], sB + row * 128 + u * 16);
            }
#pragma unroll
            for (int mt = 0; mt < 2; mt++)
#pragma unroll
                for (int nn = 0; nn < 8; nn++) {
                    const int t4 = nn >> 1, hb = nn & 1;
                    MMA(acc[mt][nn], af[mt], bf[t4][hb], bf[t4][2 + hb]);
                }
        }
        __syncthreads();
    }
    asm volatile("cp.async.wait_group %0;" :: "n"(0) : "memory");

    // ---------------- epilogue ----------------
#pragma unroll
    for (int mt = 0; mt < 2; mt++) {
#pragma unroll
        for (int hh = 0; hh < 2; hh++) {
            const int m = m0 + warp_m * 32 + mt * 16 + (lane >> 2) + hh * 8;
            float rowacc = 0.f;
            float ri = 1.f;
            if (NRM) ri = 1.0f / rsum[(size_t)batch * HW + m];
            const float bm = (BIAS == 1) ? bias[m] : 0.f;
#pragma unroll
            for (int nn = 0; nn < 8; nn++) {
                const int nc = n0 + warp_n * 64 + nn * 8 + (lane & 3) * 2;
                float v0 = acc[mt][nn][hh * 2 + 0] * alpha;
                float v1 = acc[mt][nn][hh * 2 + 1] * alpha;
                if (EXPOUT) { v0 = __expf(v0); v1 = __expf(v1); rowacc += v0 + v1; }
                if (BIAS == 1) { v0 += bm; v1 += bm; }
                if (BIAS == 2) { v0 += bias[nc]; v1 += bias[nc + 1]; }
                if (RES) {
                    const float2 rr = *(const float2*)&res[zR * batch + (size_t)m * ldC + nc];
                    v0 = (v0 + rr.x) * oscale;
                    v1 = (v1 + rr.y) * oscale;
                }
                if (NRM) { v0 *= ri; v1 *= ri; }
                if (OUTF16) {
                    __half2 hv = __floats2half2_rn(v0, v1);
                    *(__half2*)((h16*)C + coff + (size_t)m * ldC + nc) = hv;
                } else {
                    float2 f; f.x = v0; f.y = v1;
                    *(float2*)((float*)C + coff + (size_t)m * ldC + nc) = f;
                }
            }
            if (EXPOUT) {
                rowacc += __shfl_xor_sync(~0u, rowacc, 1);
                rowacc += __shfl_xor_sync(~0u, rowacc, 2);
                if ((lane & 3) == 0) atomicAdd(&rsum[(size_t)batch * HW + m], rowacc);
            }
        }
    }
}

// ---------------- fixup: ot = (ps0 + ps1) / rsum ----------------
__global__ __launch_bounds__(256)
void fixup_k(const h16* __restrict__ ps, const float* __restrict__ rs,
             h16* __restrict__ ot) {
    const size_t zT = (size_t)HW * CDIM;   // 2^21
    size_t e = ((size_t)blockIdx.x * 256 + threadIdx.x) * 8;
    int b = (int)(e >> 21);
    size_t r = e & (zT - 1);
    int t = (int)(r >> 9);
    const float ri = 1.0f / rs[(size_t)b * HW + t];

    uint4 p0 = *(const uint4*)&ps[(size_t)(2 * b) * zT + r];
    uint4 p1 = *(const uint4*)&ps[(size_t)(2 * b + 1) * zT + r];
    const __half2* a0 = (const __half2*)&p0;
    const __half2* a1 = (const __half2*)&p1;
    uint4 o;
    __half2* ov = (__half2*)&o;
#pragma unroll
    for (int i = 0; i < 4; i++) {
        float2 f0 = __half22float2(a0[i]);
        float2 f1 = __half22float2(a1[i]);
        ov[i] = __floats2half2_rn((f0.x + f1.x) * ri, (f0.y + f1.y) * ri);
    }
    *(uint4*)&ot[(size_t)b * zT + r] = o;
}

// ---------------- launch ----------------
extern "C" void kernel_launch(void* const* d_in, const int* in_sizes, int n_in,
                              void* d_out, int out_size) {
    const float* q     = (const float*)d_in[0];
    const float* gamma = (const float*)d_in[1];
    const float* beta  = (const float*)d_in[2];
    const float* wq    = (const float*)d_in[3];
    const float* bq    = (const float*)d_in[4];
    const float* wk    = (const float*)d_in[5];
    const float* bk    = (const float*)d_in[6];
    const float* wv    = (const float*)d_in[7];
    const float* bv    = (const float*)d_in[8];
    const float* wo    = (const float*)d_in[9];
    const float* bo    = (const float*)d_in[10];
    float* out = (float*)d_out;

    h16 *nrm, *qkp, *gw, *vp, *ps, *ot, *pp;
    float *rs, *bqk;
    cudaGetSymbolAddress((void**)&nrm, g_nrm);
    cudaGetSymbolAddress((void**)&qkp, g_qkp);
    cudaGetSymbolAddress((void**)&gw, g_w);
    cudaGetSymbolAddress((void**)&vp, g_vp);
    cudaGetSymbolAddress((void**)&ps, g_ps);
    cudaGetSymbolAddress((void**)&ot, g_ot);
    cudaGetSymbolAddress((void**)&pp, g_p);
    cudaGetSymbolAddress((void**)&rs, g_r);
    cudaGetSymbolAddress((void**)&bqk, g_bqk);

    cudaFuncSetAttribute(gemm16<true, 2, false, false, false, 1>, cudaFuncAttributeMaxDynamicSharedMemorySize, SMEM_TOT);
    cudaFuncSetAttribute(gemm16<true, 1, false, false, false, 0>, cudaFuncAttributeMaxDynamicSharedMemorySize, SMEM_TOT);
    cudaFuncSetAttribute(gemm16<true, 0, false, true, false, 0>,  cudaFuncAttributeMaxDynamicSharedMemorySize, SMEM_TOT);
    cudaFuncSetAttribute(gemm16<true, 0, false, false, false, 2>, cudaFuncAttributeMaxDynamicSharedMemorySize, SMEM_TOT);
    cudaFuncSetAttribute(gemm16<false, 1, true, false, false, 0>, cudaFuncAttributeMaxDynamicSharedMemorySize, SMEM_TOT);

    const size_t zT = (size_t)HW * CDIM;   // [t][c] batch stride
    const size_t zS = (size_t)HW * HW;
    const size_t W  = 262144;              // 512*512

    gn_fused<<<dim3(32, BATCH), 512>>>(q, nrm, gamma, beta);
    wconv<<<4096, 256>>>(wq, wk, wv, wo, bq, bk, gw, bqk, rs);

    // merged q+k proj: z<8: qp = qt*wq+bq; z>=8: kp = vt*wk+bk
    gemm16<true, 2, false, false, false, 1><<<dim3(4, 32, 16), 256, SMEM_TOT>>>(
        nrm, zT, CDIM, gw, 0, CDIM, qkp, zT, CDIM, CDIM,
        bqk, nullptr, 0, nullptr, 1.f, 1.f, 8 * zT, W, 8 * zT);

    // v proj: C[c_out][t] = wv[c_out][k] * vt[t][k], bias over m
    gemm16<true, 1, false, false, false, 0><<<dim3(32, 4, BATCH), 256, SMEM_TOT>>>(
        gw + 2 * W, 0, CDIM, nrm + 8 * zT, zT, CDIM, vp, zT, HW, CDIM,
        bv, nullptr, 0, nullptr, 1.f, 1.f, 0, 0, 0);

    // scores+exp: E[y][x] = exp(scale * qp[y]·kp[x]) fp16; rowsums -> rs
    const float scale = 1.f / sqrtf((float)CDIM);
    gemm16<true, 0, false, true, false, 0><<<dim3(32, 32, BATCH), 256, SMEM_TOT>>>(
        qkp, zT, CDIM, qkp + 8 * zT, zT, CDIM, pp, zS, HW, CDIM,
        nullptr, nullptr, 0, rs, scale, 1.f, 0, 0, 0);

    // PV split-K2: ps[bz][y][c] = sum_{x in half} E[y][x] * vp[c][x]
    gemm16<true, 0, false, false, false, 2><<<dim3(4, 32, 16), 256, SMEM_TOT>>>(
        pp, zS, HW, vp, zT, HW, ps, zT, CDIM, HW / 2,
        nullptr, nullptr, 0, nullptr, 1.f, 1.f, 0, 0, 0);

    // fixup: ot = (ps0 + ps1) / rs
    fixup_k<<<(int)((size_t)BATCH * zT / 8 / 256), 256>>>(ps, rs, ot);

    // out[c][t] = (wo[c][k]·ot[t][k] + bo[c] + q[c][t]) / sqrt(2)  (fp32 out)
    const float inv_sqrt2 = 0.70710678118654752440f;
    gemm16<false, 1, true, false, false, 0><<<dim3(32, 4, BATCH), 256, SMEM_TOT>>>(
        gw + 3 * W, 0, CDIM, ot, zT, CDIM, out, (size_t)CDIM * HW, HW, CDIM,
        bo, q, (size_t)CDIM * HW, nullptr, 1.f, inv_sqrt2, 0, 0, 0);
}

// round 15
// speedup vs baseline: 1.0358x; 1.0358x over previous
#include <cuda_runtime.h>
#include <cuda_fp16.h>
#include <math.h>
#include <stdint.h>

#define BATCH 8
#define CDIM 512
#define HW 4096
#define CPG 16
#define EPSV 1e-6f

typedef __half h16;

// ---------------- device scratch ----------------
// g_nrm: [0..8) GN1 out, [8..16) GN2 out, each [b][t][c]
__device__ h16   g_nrm[(size_t)16 * HW * CDIM];
// g_qkp: [0..8) q proj, [8..16) k proj, each [b][t][c]
__device__ h16   g_qkp[(size_t)16 * HW * CDIM];
__device__ h16   g_w  [(size_t)4 * CDIM * CDIM];    // wq,wk,wv,wo fp16
__device__ float g_bqk[2 * CDIM];                   // bq | bk
__device__ h16   g_vp [(size_t)BATCH * CDIM * HW];  // v proj [b][c][t]
__device__ h16   g_ot [(size_t)BATCH * HW * CDIM];  // attn out [b][t][c]
__device__ h16   g_p  [(size_t)BATCH * HW * HW];    // E = exp(scale*S) [b][y][x]
__device__ float g_r  [(size_t)BATCH * HW];         // row sums of E

// ---------------- PTX helpers ----------------
__device__ __forceinline__ uint32_t smem_u32(const void* p) {
    uint32_t a;
    asm("{ .reg .u64 t; cvta.to.shared.u64 t, %1; cvt.u32.u64 %0, t; }" : "=r"(a) : "l"(p));
    return a;
}
__device__ __forceinline__ void cpa16(uint32_t d, const void* g) {
    asm volatile("cp.async.cg.shared.global [%0], [%1], 16;" :: "r"(d), "l"(g) : "memory");
}
__device__ __forceinline__ void ldm4(uint32_t* d, uint32_t addr) {
    asm volatile("ldmatrix.sync.aligned.m8n8.x4.shared.b16 {%0,%1,%2,%3}, [%4];"
                 : "=r"(d[0]), "=r"(d[1]), "=r"(d[2]), "=r"(d[3]) : "r"(addr));
}
#define MMA(d, a, b0, b1) \
    asm volatile("mma.sync.aligned.m16n8k16.row.col.f32.f16.f16.f32 " \
        "{%0,%1,%2,%3}, {%4,%5,%6,%7}, {%8,%9}, {%0,%1,%2,%3};" \
        : "+f"((d)[0]), "+f"((d)[1]), "+f"((d)[2]), "+f"((d)[3]) \
        : "r"((a)[0]), "r"((a)[1]), "r"((a)[2]), "r"((a)[3]), "r"(b0), "r"(b1))

// ---------------- fused double GroupNorm ----------------
__global__ __launch_bounds__(512)
void gn_fused(const float* __restrict__ x, h16* __restrict__ nrm,
              const float* __restrict__ gamma, const float* __restrict__ beta) {
    const int grp = blockIdx.x, b = blockIdx.y;
    const int c0 = grp * CPG;
    const size_t base = ((size_t)b * CDIM + c0) * HW;
    const int tid = threadIdx.x, wid = tid >> 5, lane = tid & 31;

    const float4* xc = (const float4*)(x + base + (size_t)wid * HW);
    float s = 0.f, ss = 0.f;
    for (int i = lane; i < HW / 4; i += 32) {
        float4 v = xc[i];
        s  += v.x + v.y + v.z + v.w;
        ss += v.x * v.x + v.y * v.y + v.z * v.z + v.w * v.w;
    }
#pragma unroll
    for (int o = 16; o; o >>= 1) {
        s  += __shfl_xor_sync(~0u, s, o);
        ss += __shfl_xor_sync(~0u, ss, o);
    }
    __shared__ float Sc[CPG], Qc[CPG];
    __shared__ float A1[CPG], B1[CPG], A2[CPG], B2[CPG];
    if (lane == 0) { Sc[wid] = s; Qc[wid] = ss; }
    __syncthreads();
    if (tid == 0) {
        float St = 0.f, Qt = 0.f;
        for (int c = 0; c < CPG; c++) { St += Sc[c]; Qt += Qc[c]; }
        const float invN = 1.f / (float)(CPG * HW);
        float mu1 = St * invN;
        float r1 = rsqrtf(Qt * invN - mu1 * mu1 + EPSV);
        float s2 = 0.f, q2 = 0.f;
        for (int c = 0; c < CPG; c++) {
            float a1 = gamma[c0 + c] * r1;
            float b1 = beta[c0 + c] - mu1 * a1;
            A1[c] = a1; B1[c] = b1;
            s2 += a1 * Sc[c] + (float)HW * b1;
            q2 += a1 * a1 * Qc[c] + 2.f * a1 * b1 * Sc[c] + (float)HW * b1 * b1;
        }
        float mu2 = s2 * invN;
        float r2 = rsqrtf(q2 * invN - mu2 * mu2 + EPSV);
        for (int c = 0; c < CPG; c++) {
            float g = gamma[c0 + c];
            A2[c] = g * r2 * A1[c];
            B2[c] = g * r2 * (B1[c] - mu2) + beta[c0 + c];
        }
    }
    __syncthreads();

    h16* qh = nrm + (size_t)b * HW * CDIM;
    h16* vh = nrm + (size_t)(8 + b) * HW * CDIM;
    for (int t = tid; t < HW; t += 512) {
        alignas(16) h16 h1[CPG], h2[CPG];
#pragma unroll
        for (int c = 0; c < CPG; c++) {
            float v = x[base + (size_t)c * HW + t];
            h1[c] = __float2half_rn(fmaf(v, A1[c], B1[c]));
            h2[c] = __float2half_rn(fmaf(v, A2[c], B2[c]));
        }
        size_t o = (size_t)t * CDIM + c0;
        *(uint4*)&qh[o] = *(uint4*)&h1[0]; *(uint4*)&qh[o + 8] = *(uint4*)&h1[8];
        *(uint4*)&vh[o] = *(uint4*)&h2[0]; *(uint4*)&vh[o + 8] = *(uint4*)&h2[8];
    }
}

// ---------------- weight fp32 -> fp16, bias pack, zero row sums ----------------
__global__ void wconv(const float* __restrict__ wq, const float* __restrict__ wk,
                      const float* __restrict__ wv, const float* __restrict__ wo,
                      const float* __restrict__ bq, const float* __restrict__ bk,
                      h16* __restrict__ out, float* __restrict__ bqk,
                      float* __restrict__ rz) {
    int e = blockIdx.x * 256 + threadIdx.x;
    int w = e >> 18, i = e & 0x3FFFF;
    const float* src = (w == 0) ? wq : (w == 1) ? wk : (w == 2) ? wv : wo;
    out[(size_t)w * 262144 + i] = __float2half_rn(src[i]);
    if (e < BATCH * HW) rz[e] = 0.f;
    if (e < 2 * CDIM) bqk[e] = (e < CDIM) ? bq[e] : bk[e - CDIM];
}

// ---------------- fp16 HMMA GEMM ----------------
// C[m][n] = f(alpha * sum_k A[m][k]*B[n][k])
// 128x128 block, BK=64, 3-stage cp.async (single-sync mainloop), 8 warps
// MODE 0: bz = batch
// MODE 3: fused projections; bz: batch=bz&7, sel=bz>>3 in {0:q, 1:k, 2:v}
//   sel<2: A=nrm(+sel*mA), B=w(+sel*mB), C=qkp(+sel*mC), bias over n (bias+sel*CDIM)
//   sel=2: A=w+2*mB (wv), B=nrm+mA (vt), C=g_vp [c][t] (ldc=HW), bias over m from rsum(=bv)
#define SA_BYTES 16384
#define ST_BYTES 32768
#define SMEM_TOT (3 * ST_BYTES)

template <bool OUTF16, int BIAS, bool RES, bool EXPOUT, bool NRM, int MODE>
__global__ __launch_bounds__(256, 2)
void gemm16(const h16* __restrict__ A, size_t zA, int lda,
            const h16* __restrict__ B, size_t zB, int ldb,
            void* __restrict__ C, size_t zC, int ldC, int K,
            const float* __restrict__ bias,
            const float* __restrict__ res, size_t zR,
            float* __restrict__ rsum,
            float alpha, float oscale,
            size_t mA, size_t mB, size_t mC) {
    extern __shared__ __align__(16) char smem[];
    const int tid = threadIdx.x, lane = tid & 31, wid = tid >> 5;
    const int warp_m = wid & 3, warp_n = wid >> 2;
    const int bz = blockIdx.z;

    int batch = bz, sel = 0;
    if (MODE == 3) { batch = bz & 7; sel = bz >> 3; }
    const bool vmode = (MODE == 3) && (sel == 2);

    int m0, n0;
    if (vmode) { m0 = blockIdx.x * 128; n0 = blockIdx.y * 128; }
    else       { m0 = blockIdx.y * 128; n0 = blockIdx.x * 128; }
    const uint32_t sbase = smem_u32(smem);

    const h16 *Ab, *Bb;
    size_t coff;
    if (MODE == 3) {
        if (sel < 2) { Ab = A + zA * batch + (size_t)sel * mA; Bb = B + (size_t)sel * mB; }
        else         { Ab = B + 2 * mB;                        Bb = A + zA * batch + mA; }
        coff = zC * (size_t)batch + (vmode ? 0 : (size_t)sel * mC);
    } else {
        Ab = A + zA * batch;
        Bb = B + zB * batch;
        coff = zC * (size_t)batch;
    }

    const int nst = K >> 6;

    // hoisted loader addressing: per-thread row/XOR invariant across i (i*32 % 8 == 0)
    const int trow = tid >> 3;
    const uint32_t tu = (uint32_t)(tid & 7) ^ ((uint32_t)trow & 7);
    const h16* gA = Ab + (size_t)(m0 + trow) * lda + (tid & 7) * 8;
    const h16* gB = Bb + (size_t)(n0 + trow) * ldb + (tid & 7) * 8;
    const uint32_t soff = (uint32_t)trow * 128 + tu * 16;
    const size_t stepA = (size_t)32 * lda;
    const size_t stepB = (size_t)32 * ldb;

    auto load_stage = [&](int stage, int k0) {
        const uint32_t sA = sbase + stage * ST_BYTES;
        const uint32_t sB = sA + SA_BYTES;
#pragma unroll
        for (int i = 0; i < 4; i++) {
            cpa16(sA + soff + i * 4096, gA + (size_t)i * stepA + k0);
            cpa16(sB + soff + i * 4096, gB + (size_t)i * stepB + k0);
        }
    };

    float acc[2][8][4];
#pragma unroll
    for (int i = 0; i < 2; i++)
#pragma unroll
        for (int j = 0; j < 8; j++)
#pragma unroll
            for (int l = 0; l < 4; l++) acc[i][j][l] = 0.f;

    load_stage(0, 0);
    asm volatile("cp.async.commit_group;" ::: "memory");
    load_stage(1, 64);
    asm volatile("cp.async.commit_group;" ::: "memory");

    const int g = lane >> 3, r = lane & 7;

    for (int s = 0; s < nst; s++) {
        asm volatile("cp.async.wait_group %0;" :: "n"(1) : "memory");
        __syncthreads();
        if (s + 2 < nst) load_stage((s + 2) % 3, (s + 2) << 6);
        asm volatile("cp.async.commit_group;" ::: "memory");

        const uint32_t sA = sbase + (s % 3) * ST_BYTES;
        const uint32_t sB = sA + SA_BYTES;
#pragma unroll
        for (int kk = 0; kk < 4; kk++) {
            const int c0 = kk * 16 + (g >> 1) * 8;
            const int uu = c0 >> 3;
            uint32_t af[2][4], bf[4][4];
#pragma unroll
            for (int mt = 0; mt < 2; mt++) {
                const int row = warp_m * 32 + mt * 16 + r + (g & 1) * 8;
                const uint32_t u = (uint32_t)uu ^ (row & 7);
                ldm4(af[mt], sA + row * 128 + u * 16);
            }
#pragma unroll
            for (int nt = 0; nt < 4; nt++) {
                const int row = warp_n * 64 + nt * 16 + r + (g & 1) * 8;
                const uint32_t u = (uint32_t)uu ^ (row & 7);
                ldm4(bf[nt], sB + row * 128 + u * 16);
            }
#pragma unroll
            for (int mt = 0; mt < 2; mt++)
#pragma unroll
                for (int nn = 0; nn < 8; nn++) {
                    const int t4 = nn >> 1, hb = nn & 1;
                    MMA(acc[mt][nn], af[mt], bf[t4][hb], bf[t4][2 + hb]);
                }
        }
        // no bottom sync: next iteration's top barrier retires this stage (CUTLASS-style)
    }
    asm volatile("cp.async.wait_group %0;" :: "n"(0) : "memory");

    // ---------------- epilogue ----------------
    h16* Cb16 = vmode ? (h16*)g_vp : (h16*)C;
    const int ldc = vmode ? HW : ldC;
    const float* biasn = (MODE == 3) ? bias + sel * CDIM : bias;

#pragma unroll
    for (int mt = 0; mt < 2; mt++) {
#pragma unroll
        for (int hh = 0; hh < 2; hh++) {
            const int m = m0 + warp_m * 32 + mt * 16 + (lane >> 2) + hh * 8;
            float rowacc = 0.f;
            float ri = 1.f;
            if (NRM) ri = 1.0f / rsum[(size_t)batch * HW + m];
            float bm = 0.f;
            if (BIAS == 1) bm = bias[m];
            if (vmode) bm = rsum[m];     // bv passed via rsum slot in MODE 3
#pragma unroll
            for (int nn = 0; nn < 8; nn++) {
                const int nc = n0 + warp_n * 64 + nn * 8 + (lane & 3) * 2;
                float v0 = acc[mt][nn][hh * 2 + 0] * alpha;
                float v1 = acc[mt][nn][hh * 2 + 1] * alpha;
                if (EXPOUT) { v0 = __expf(v0); v1 = __expf(v1); rowacc += v0 + v1; }
                v0 += bm; v1 += bm;
                if (BIAS == 2) {
                    if (!vmode) { v0 += biasn[nc]; v1 += biasn[nc + 1]; }
                }
                if (RES) {
                    const float2 rr = *(const float2*)&res[zR * batch + (size_t)m * ldc + nc];
                    v0 = (v0 + rr.x) * oscale;
                    v1 = (v1 + rr.y) * oscale;
                }
                if (NRM) { v0 *= ri; v1 *= ri; }
                if (OUTF16) {
                    __half2 hv = __floats2half2_rn(v0, v1);
                    *(__half2*)(Cb16 + coff + (size_t)m * ldc + nc) = hv;
                } else {
                    float2 f; f.x = v0; f.y = v1;
                    *(float2*)((float*)C + coff + (size_t)m * ldc + nc) = f;
                }
            }
            if (EXPOUT) {
                rowacc += __shfl_xor_sync(~0u, rowacc, 1);
                rowacc += __shfl_xor_sync(~0u, rowacc, 2);
                if ((lane & 3) == 0) atomicAdd(&rsum[(size_t)batch * HW + m], rowacc);
            }
        }
    }
}

// ---------------- launch ----------------
extern "C" void kernel_launch(void* const* d_in, const int* in_sizes, int n_in,
                              void* d_out, int out_size) {
    const float* q     = (const float*)d_in[0];
    const float* gamma = (const float*)d_in[1];
    const float* beta  = (const float*)d_in[2];
    const float* wq    = (const float*)d_in[3];
    const float* bq    = (const float*)d_in[4];
    const float* wk    = (const float*)d_in[5];
    const float* bk    = (const float*)d_in[6];
    const float* wv    = (const float*)d_in[7];
    const float* bv    = (const float*)d_in[8];
    const float* wo    = (const float*)d_in[9];
    const float* bo    = (const float*)d_in[10];
    float* out = (float*)d_out;

    h16 *nrm, *qkp, *gw, *vp, *ot, *pp;
    float *rs, *bqk;
    cudaGetSymbolAddress((void**)&nrm, g_nrm);
    cudaGetSymbolAddress((void**)&qkp, g_qkp);
    cudaGetSymbolAddress((void**)&gw, g_w);
    cudaGetSymbolAddress((void**)&vp, g_vp);
    cudaGetSymbolAddress((void**)&ot, g_ot);
    cudaGetSymbolAddress((void**)&pp, g_p);
    cudaGetSymbolAddress((void**)&rs, g_r);
    cudaGetSymbolAddress((void**)&bqk, g_bqk);

    cudaFuncSetAttribute(gemm16<true, 2, false, false, false, 3>, cudaFuncAttributeMaxDynamicSharedMemorySize, SMEM_TOT);
    cudaFuncSetAttribute(gemm16<true, 0, false, true, false, 0>,  cudaFuncAttributeMaxDynamicSharedMemorySize, SMEM_TOT);
    cudaFuncSetAttribute(gemm16<true, 0, false, false, true, 0>,  cudaFuncAttributeMaxDynamicSharedMemorySize, SMEM_TOT);
    cudaFuncSetAttribute(gemm16<false, 1, true, false, false, 0>, cudaFuncAttributeMaxDynamicSharedMemorySize, SMEM_TOT);

    const size_t zT = (size_t)HW * CDIM;   // [t][c] batch stride
    const size_t zS = (size_t)HW * HW;
    const size_t W  = 262144;              // 512*512

    gn_fused<<<dim3(32, BATCH), 512>>>(q, nrm, gamma, beta);
    wconv<<<4096, 256>>>(wq, wk, wv, wo, bq, bk, gw, bqk, rs);

    // fused projections: z<8 q, z<16 k, z<24 v (v -> g_vp [c][t], bias bv via rsum slot)
    gemm16<true, 2, false, false, false, 3><<<dim3(4, 32, 24), 256, SMEM_TOT>>>(
        nrm, zT, CDIM, gw, 0, CDIM, qkp, zT, CDIM, CDIM,
        bqk, nullptr, 0, (float*)bv, 1.f, 1.f, 8 * zT, W, 8 * zT);

    // scores+exp: E[y][x] = exp(scale * qp[y]·kp[x]) fp16; rowsums -> rs
    const float scale = 1.f / sqrtf((float)CDIM);
    gemm16<true, 0, false, true, false, 0><<<dim3(32, 32, BATCH), 256, SMEM_TOT>>>(
        qkp, zT, CDIM, qkp + 8 * zT, zT, CDIM, pp, zS, HW, CDIM,
        nullptr, nullptr, 0, rs, scale, 1.f, 0, 0, 0);

    // attn out: ot[y][c] = (sum_x E[y][x] * vp[c][x]) / rs[y]
    gemm16<true, 0, false, false, true, 0><<<dim3(4, 32, BATCH), 256, SMEM_TOT>>>(
        pp, zS, HW, vp, zT, HW, ot, zT, CDIM, HW,
        nullptr, nullptr, 0, rs, 1.f, 1.f, 0, 0, 0);

    // out[c][t] = (wo[c][k]·ot[t][k] + bo[c] + q[c][t]) / sqrt(2)  (fp32 out)
    const float inv_sqrt2 = 0.70710678118654752440f;
    gemm16<false, 1, true, false, false, 0><<<dim3(32, 4, BATCH), 256, SMEM_TOT>>>(
        gw + 3 * W, 0, CDIM, ot, zT, CDIM, out, (size_t)CDIM * HW, HW, CDIM,
        bo, q, (size_t)CDIM * HW, nullptr, 1.f, inv_sqrt2, 0, 0, 0);
}